// round 13
// baseline (speedup 1.0000x reference)
#include <cuda_runtime.h>
#include <cuda_fp16.h>
#include <math.h>
#include <stdint.h>

#define N_NODES 50000
#define N_EDGES 1600000
#define IN_F    512
#define NH      128
#define NC      40
#define SCAN_B  ((N_NODES + 255) / 256)   // 196 blocks
#define N_HALF  25000

// ---------------- static scratch (no runtime allocation) ----------------
__device__ int      g_deg_out_i[N_NODES];
__device__ int      g_deg_in_i [N_NODES];
__device__ int      g_cursor   [N_NODES];
__device__ int      g_row_ptr  [N_NODES + 1];
__device__ int      g_bsum     [256];
__device__ int      g_boff     [256];
__device__ int2     g_edge     [N_EDGES];           // (src, bits(ns[src])) grouped by dst
__device__ float    g_ns       [N_NODES];
__device__ float    g_nd       [N_NODES];
__device__ uint16_t g_w1t_hi   [NH * IN_F];         // W1^T fp16, [n][k]
__device__ __half   g_h1       [(size_t)N_NODES * NH]; // X@W1 (unscaled, fp16)
__device__ float    g_x2       [(size_t)N_NODES * NH]; // relu(agg1*nd + b1)
__device__ __half   g_h2h      [(size_t)N_NODES * NC]; // x2@W2 (unscaled, fp16)

// ---------------- small helpers ----------------
__device__ __forceinline__ uint32_t smem_to_u32(const void* p) {
    uint32_t a;
    asm("{ .reg .u64 t; cvta.to.shared.u64 t, %1; cvt.u32.u64 %0, t; }" : "=r"(a) : "l"(p));
    return a;
}
__device__ __forceinline__ void ldmx4(uint32_t* r, uint32_t addr) {
    asm volatile("ldmatrix.sync.aligned.m8n8.x4.shared.b16 {%0,%1,%2,%3}, [%4];"
                 : "=r"(r[0]), "=r"(r[1]), "=r"(r[2]), "=r"(r[3]) : "r"(addr));
}
__device__ __forceinline__ void mma_f16(float* d, const uint32_t* a, const uint32_t* b) {
    asm volatile(
        "mma.sync.aligned.m16n8k16.row.col.f32.f16.f16.f32 "
        "{%0,%1,%2,%3}, {%4,%5,%6,%7}, {%8,%9}, {%0,%1,%2,%3};"
        : "+f"(d[0]), "+f"(d[1]), "+f"(d[2]), "+f"(d[3])
        : "r"(a[0]), "r"(a[1]), "r"(a[2]), "r"(a[3]), "r"(b[0]), "r"(b[1]));
}
__device__ __forceinline__ unsigned long long pack2(float x) {
    unsigned long long r;
    asm("mov.b64 %0, {%1, %1};" : "=l"(r) : "f"(x));
    return r;
}
__device__ __forceinline__ unsigned long long packf2(float lo, float hi) {
    unsigned long long r;
    asm("mov.b64 %0, {%1, %2};" : "=l"(r) : "f"(lo), "f"(hi));
    return r;
}
__device__ __forceinline__ void fma2(unsigned long long& d,
                                     unsigned long long a, unsigned long long b) {
    asm("fma.rn.f32x2 %0, %1, %2, %0;" : "+l"(d) : "l"(a), "l"(b));
}
__device__ __forceinline__ float2 unpack2(unsigned long long v) {
    float lo, hi;
    asm("mov.b64 {%0, %1}, %2;" : "=f"(lo), "=f"(hi) : "l"(v));
    return make_float2(lo, hi);
}

// ---------------- zero counters each call ----------------
__global__ void zero_kernel() {
    int i = blockIdx.x * blockDim.x + threadIdx.x;
    int stride = gridDim.x * blockDim.x;
    for (int j = i; j < N_NODES; j += stride) {
        g_deg_out_i[j] = 0;
        g_deg_in_i [j] = 0;
        g_cursor   [j] = 0;
    }
}

__global__ void deg_kernel(const int* __restrict__ src, const int* __restrict__ dst) {
    int e = blockIdx.x * blockDim.x + threadIdx.x;
    if (e < N_EDGES) {
        atomicAdd(&g_deg_out_i[src[e]], 1);
        atomicAdd(&g_deg_in_i [dst[e]], 1);
    }
}

__global__ void norm_kernel() {
    int i = blockIdx.x * blockDim.x + threadIdx.x;
    if (i < N_NODES) {
        g_ns[i] = rsqrtf(fmaxf((float)g_deg_out_i[i], 1.f));
        g_nd[i] = rsqrtf(fmaxf((float)g_deg_in_i [i], 1.f));
    }
}

// ---------------- hierarchical scan: deg_in -> row_ptr ----------------
__global__ __launch_bounds__(256) void scan1_kernel() {
    __shared__ int s[256];
    int i = blockIdx.x * 256 + threadIdx.x;
    s[threadIdx.x] = (i < N_NODES) ? g_deg_in_i[i] : 0;
    __syncthreads();
    for (int off = 128; off > 0; off >>= 1) {
        if (threadIdx.x < off) s[threadIdx.x] += s[threadIdx.x + off];
        __syncthreads();
    }
    if (threadIdx.x == 0) g_bsum[blockIdx.x] = s[0];
}

__global__ __launch_bounds__(256) void scan2_kernel() {
    __shared__ int s[256];
    int t = threadIdx.x;
    int v = (t < SCAN_B) ? g_bsum[t] : 0;
    s[t] = v;
    __syncthreads();
    for (int off = 1; off < 256; off <<= 1) {
        int u = (t >= off) ? s[t - off] : 0;
        __syncthreads();
        s[t] += u;
        __syncthreads();
    }
    g_boff[t] = s[t] - v;
    if (t == 255) g_row_ptr[N_NODES] = s[255];
}

__global__ __launch_bounds__(256) void scan3_kernel() {
    __shared__ int s[256];
    int t = threadIdx.x;
    int i = blockIdx.x * 256 + t;
    int v = (i < N_NODES) ? g_deg_in_i[i] : 0;
    s[t] = v;
    __syncthreads();
    for (int off = 1; off < 256; off <<= 1) {
        int u = (t >= off) ? s[t - off] : 0;
        __syncthreads();
        s[t] += u;
        __syncthreads();
    }
    if (i < N_NODES) g_row_ptr[i] = g_boff[blockIdx.x] + s[t] - v;
}

__global__ void fill_kernel(const int* __restrict__ src, const int* __restrict__ dst) {
    int e = blockIdx.x * blockDim.x + threadIdx.x;
    if (e < N_EDGES) {
        int d = dst[e];
        int s = src[e];
        int pos = g_row_ptr[d] + atomicAdd(&g_cursor[d], 1);
        g_edge[pos] = make_int2(s, __float_as_int(g_ns[s]));
    }
}

// ---------------- W1 -> transposed fp16 ----------------
__global__ void w1split_kernel(const float* __restrict__ W1) {
    int i = blockIdx.x * 256 + threadIdx.x;     // over 512*128
    if (i < IN_F * NH) {
        int k = i >> 7, n = i & 127;
        __half h = __float2half_rn(W1[i]);
        g_w1t_hi[n * IN_F + k] = __half_as_ushort(h);
    }
}

// ---------------- GEMM1: h1 = X @ W1 via plain fp16 mma.sync ---------------
// CTA 128x128, 8 warps (4M x 2N), warp 32x64, K-chunk 32, 2 stages.
// smem stage (16KB): A[128][32]f16 @0, B[128n][32k]f16 @8192.
#define G1M_STAGE 16384
#define G1M_SMEM  (2 * G1M_STAGE)

__global__ __launch_bounds__(256) void gemm1_mma_kernel(const float* __restrict__ X) {
    extern __shared__ char smem[];
    const uint32_t sb = smem_to_u32(smem);
    const int tid  = threadIdx.x;
    const int lane = tid & 31;
    const int wid  = tid >> 5;
    const int bm   = blockIdx.x * 128;
    const int mw   = (wid & 3) * 32;     // warp M offset
    const int nw   = (wid >> 2) * 64;    // warp N offset

    float acc[2][8][4];
    #pragma unroll
    for (int i = 0; i < 2; i++)
        #pragma unroll
        for (int j = 0; j < 8; j++)
            #pragma unroll
            for (int q = 0; q < 4; q++) acc[i][j][q] = 0.f;

    const int lrow  = tid >> 1;
    const int lhalf = tid & 1;
    const int lsw   = (lrow >> 1) & 3;

    auto load_stage = [&](int st, int k0) {
        char* stg = smem + st * G1M_STAGE;
        // A: X rows -> fp16
        {
            const int gr = bm + lrow;
            const bool ok = gr < N_NODES;
            const float* xp = &X[(size_t)gr * IN_F + k0 + lhalf * 16];
            #pragma unroll
            for (int q = 0; q < 4; q++) {
                float4 v = ok ? *reinterpret_cast<const float4*>(xp + q * 4)
                              : make_float4(0.f, 0.f, 0.f, 0.f);
                __half2 ha = __floats2half2_rn(v.x, v.y);
                __half2 hb = __floats2half2_rn(v.z, v.w);
                uint32_t hau, hbu;
                memcpy(&hau, &ha, 4); memcpy(&hbu, &hb, 4);
                int c16 = lhalf * 2 + (q >> 1);
                uint32_t off = (uint32_t)(lrow * 64 + ((c16 ^ lsw) * 16) + (q & 1) * 8);
                *reinterpret_cast<uint2*>(stg + off) = make_uint2(hau, hbu);
            }
        }
        // B: pre-converted W1^T fp16, copy 32-k slice
        {
            const uint16_t* bh = &g_w1t_hi[lrow * IN_F + k0 + lhalf * 16];
            #pragma unroll
            for (int q = 0; q < 2; q++) {
                uint4 hv = *reinterpret_cast<const uint4*>(bh + q * 8);
                int c16 = lhalf * 2 + q;
                uint32_t off = (uint32_t)(lrow * 64 + ((c16 ^ lsw) * 16));
                *reinterpret_cast<uint4*>(stg + 8192 + off) = hv;
            }
        }
    };

    load_stage(0, 0);
    __syncthreads();

    const int a_rlane = lane & 15;
    const int a_kg    = lane >> 4;
    const int b_grp   = lane >> 3;
    const int b_rlane = (b_grp >> 1) * 8 + (lane & 7);
    const int b_kg    = b_grp & 1;

    const int NCHUNK = IN_F / 32;           // 16
    for (int c = 0; c < NCHUNK; c++) {
        const int cur = c & 1;
        if (c + 1 < NCHUNK) load_stage(cur ^ 1, (c + 1) * 32);

        const uint32_t sbase = sb + cur * G1M_STAGE;
        #pragma unroll
        for (int ks = 0; ks < 2; ks++) {
            uint32_t A[2][4];
            #pragma unroll
            for (int mt = 0; mt < 2; mt++) {
                int row = mw + mt * 16 + a_rlane;
                uint32_t byteoff = (uint32_t)(row * 64 +
                    (((ks * 2 + a_kg) ^ ((row >> 1) & 3)) * 16));
                ldmx4(A[mt], sbase + byteoff);
            }
            uint32_t B[8][2];
            #pragma unroll
            for (int ntp = 0; ntp < 4; ntp++) {
                int n = nw + ntp * 16 + b_rlane;
                uint32_t byteoff = (uint32_t)(n * 64 +
                    (((ks * 2 + b_kg) ^ ((n >> 1) & 3)) * 16));
                uint32_t rh[4];
                ldmx4(rh, sbase + 8192 + byteoff);
                B[ntp * 2][0] = rh[0]; B[ntp * 2][1] = rh[1];
                B[ntp * 2 + 1][0] = rh[2]; B[ntp * 2 + 1][1] = rh[3];
            }
            #pragma unroll
            for (int mt = 0; mt < 2; mt++)
                #pragma unroll
                for (int nt = 0; nt < 8; nt++)
                    mma_f16(acc[mt][nt], A[mt], B[nt]);
        }
        __syncthreads();
    }

    // epilogue: convert to fp16 and store half2 per 2 cols
    #pragma unroll
    for (int mt = 0; mt < 2; mt++) {
        int row = bm + mw + mt * 16 + (lane >> 2);
        #pragma unroll
        for (int nt = 0; nt < 8; nt++) {
            int col = nw + nt * 8 + (lane & 3) * 2;
            __half2 p0 = __floats2half2_rn(acc[mt][nt][0], acc[mt][nt][1]);
            __half2 p1 = __floats2half2_rn(acc[mt][nt][2], acc[mt][nt][3]);
            if (row < N_NODES)
                *reinterpret_cast<__half2*>(&g_h1[(size_t)row * NH + col]) = p0;
            if (row + 8 < N_NODES)
                *reinterpret_cast<__half2*>(&g_h1[(size_t)(row + 8) * NH + col]) = p1;
        }
    }
}

// ---------------- agg1: paired-edge uint4 gather, fp32 accum ---------------
__global__ void agg1_kernel(const float* __restrict__ b1, int base, int count) {
    int t = blockIdx.x * blockDim.x + threadIdx.x;
    int w = (t >> 5);
    int lane = t & 31;
    if (w >= count) return;
    w += base;
    int beg = g_row_ptr[w], end = g_row_ptr[w + 1];

    const int half = lane >> 4;
    const int li   = lane & 15;

    unsigned long long a0 = 0ull, a1 = 0ull, a2 = 0ull, a3 = 0ull;
    for (int j = beg; j < end; j += 32) {
        int n = end - j; if (n > 32) n = 32;
        int2 ed = (j + lane < end) ? g_edge[j + lane] : make_int2(0, 0);
        #pragma unroll 8
        for (int i = 0; i < n; i += 2) {
            int e  = i + half;
            int   s = __shfl_sync(0xffffffffu, ed.x, e & 31);
            float f = __int_as_float(__shfl_sync(0xffffffffu, ed.y, e & 31));
            if (e >= n) { f = 0.f; s = 0; }
            uint4 v = __ldg(reinterpret_cast<const uint4*>(&g_h1[(size_t)s * NH]) + li);
            float2 f0 = __half22float2(*reinterpret_cast<__half2*>(&v.x));
            float2 f1 = __half22float2(*reinterpret_cast<__half2*>(&v.y));
            float2 f2 = __half22float2(*reinterpret_cast<__half2*>(&v.z));
            float2 f3 = __half22float2(*reinterpret_cast<__half2*>(&v.w));
            unsigned long long pf = pack2(f);
            fma2(a0, pf, packf2(f0.x, f0.y));
            fma2(a1, pf, packf2(f1.x, f1.y));
            fma2(a2, pf, packf2(f2.x, f2.y));
            fma2(a3, pf, packf2(f3.x, f3.y));
        }
    }
    unsigned long long c0 = __shfl_xor_sync(0xffffffffu, a0, 16);
    unsigned long long c1 = __shfl_xor_sync(0xffffffffu, a1, 16);
    unsigned long long c2 = __shfl_xor_sync(0xffffffffu, a2, 16);
    unsigned long long c3 = __shfl_xor_sync(0xffffffffu, a3, 16);
    float2 q0 = unpack2(a0), r0 = unpack2(c0);
    float2 q1 = unpack2(a1), r1 = unpack2(c1);
    float2 q2 = unpack2(a2), r2 = unpack2(c2);
    float2 q3 = unpack2(a3), r3 = unpack2(c3);

    if (half == 0) {
        float nd = g_nd[w];
        int fb = li * 8;
        float4 bA = __ldg(reinterpret_cast<const float4*>(b1 + fb));
        float4 bB = __ldg(reinterpret_cast<const float4*>(b1 + fb + 4));
        float4 oA, oB;
        oA.x = fmaxf((q0.x + r0.x) * nd + bA.x, 0.f);
        oA.y = fmaxf((q0.y + r0.y) * nd + bA.y, 0.f);
        oA.z = fmaxf((q1.x + r1.x) * nd + bA.z, 0.f);
        oA.w = fmaxf((q1.y + r1.y) * nd + bA.w, 0.f);
        oB.x = fmaxf((q2.x + r2.x) * nd + bB.x, 0.f);
        oB.y = fmaxf((q2.y + r2.y) * nd + bB.y, 0.f);
        oB.z = fmaxf((q3.x + r3.x) * nd + bB.z, 0.f);
        oB.w = fmaxf((q3.y + r3.y) * nd + bB.w, 0.f);
        *reinterpret_cast<float4*>(&g_x2[(size_t)w * NH + fb])     = oA;
        *reinterpret_cast<float4*>(&g_x2[(size_t)w * NH + fb + 4]) = oB;
    }
}

// ---------------- GEMM2 over [base, base+count): fp16 output ----------------
__global__ __launch_bounds__(256) void gemm2_kernel(const float* __restrict__ W2,
                                                    int base, int count) {
    __shared__ float W2s[NH * NC];
    __shared__ float xs[8][NH];

    int tid = threadIdx.x;
    for (int i = tid; i < NH * NC; i += 256) W2s[i] = W2[i];
    __syncthreads();

    const int n_tiles = (count + 7) / 8;
    for (int tile = blockIdx.x; tile < n_tiles; tile += gridDim.x) {
        int row0 = base + tile * 8;
        int lim  = base + count;
        #pragma unroll
        for (int i = 0; i < 4; i++) {
            int j = tid + i * 256;
            int r = j >> 7, k = j & 127;
            int row = row0 + r;
            xs[r][k] = (row < lim) ? g_x2[(size_t)row * NH + k] : 0.f;
        }
        __syncthreads();

        if (tid < 8 * (NC / 2)) {
            int r  = tid / (NC / 2);
            int cp = tid % (NC / 2);
            int row = row0 + r;
            if (row < lim) {
                unsigned long long acc = 0ull;
                const unsigned long long* wp =
                    reinterpret_cast<const unsigned long long*>(W2s) + cp;
                #pragma unroll 8
                for (int k = 0; k < NH; k++)
                    fma2(acc, pack2(xs[r][k]), wp[k * (NC / 2)]);
                float2 p = unpack2(acc);
                *reinterpret_cast<__half2*>(&g_h2h[(size_t)row * NC + cp * 2]) =
                    __floats2half2_rn(p.x, p.y);
            }
        }
        __syncthreads();
    }
}

// ---------------- agg2: fp16 gather; lanes 0-19 own 2 feats each -----------
__global__ void agg2_kernel(const float* __restrict__ b2, float* __restrict__ out) {
    int t = blockIdx.x * blockDim.x + threadIdx.x;
    int w = t >> 5, lane = t & 31;
    if (w >= N_NODES) return;
    int beg = g_row_ptr[w], end = g_row_ptr[w + 1];

    unsigned long long acc = 0ull;
    const bool act = lane < (NC / 2);
    for (int j = beg; j < end; j += 32) {
        int n = end - j; if (n > 32) n = 32;
        int2 ed = (j + lane < end) ? g_edge[j + lane] : make_int2(0, 0);
        #pragma unroll 8
        for (int i = 0; i < n; i++) {
            int   s = __shfl_sync(0xffffffffu, ed.x, i);
            float f = __int_as_float(__shfl_sync(0xffffffffu, ed.y, i));
            if (act) {
                uint32_t v = __ldg(reinterpret_cast<const uint32_t*>(
                    &g_h2h[(size_t)s * NC]) + lane);
                float2 fv = __half22float2(*reinterpret_cast<__half2*>(&v));
                fma2(acc, pack2(f), packf2(fv.x, fv.y));
            }
        }
    }
    if (act) {
        float nd = g_nd[w];
        float2 p = unpack2(acc);
        float2 bb = __ldg(reinterpret_cast<const float2*>(b2) + lane);
        *reinterpret_cast<float2*>(&out[(size_t)w * NC + lane * 2]) =
            make_float2(p.x * nd + bb.x, p.y * nd + bb.y);
    }
}

// ---------------- launch ----------------
extern "C" void kernel_launch(void* const* d_in, const int* in_sizes, int n_in,
                              void* d_out, int out_size) {
    const float* X   = (const float*)d_in[0];
    const float* W1  = (const float*)d_in[1];
    const float* b1  = (const float*)d_in[2];
    const float* W2  = (const float*)d_in[3];
    const float* b2  = (const float*)d_in[4];
    const int*   src = (const int*)  d_in[5];
    const int*   dst = (const int*)  d_in[6];
    float* out = (float*)d_out;

    static cudaStream_t s_side = nullptr;
    static cudaEvent_t  ev_fork = nullptr, ev_join = nullptr;
    static cudaEvent_t  ev_a = nullptr, ev_g2a = nullptr;
    if (s_side == nullptr) {
        cudaStreamCreateWithFlags(&s_side, cudaStreamNonBlocking);
        cudaEventCreateWithFlags(&ev_fork, cudaEventDisableTiming);
        cudaEventCreateWithFlags(&ev_join, cudaEventDisableTiming);
        cudaEventCreateWithFlags(&ev_a, cudaEventDisableTiming);
        cudaEventCreateWithFlags(&ev_g2a, cudaEventDisableTiming);
        cudaFuncSetAttribute(gemm1_mma_kernel,
                             cudaFuncAttributeMaxDynamicSharedMemorySize, G1M_SMEM);
    }

    // fork: side stream runs the graph-prep chain
    cudaEventRecord(ev_fork, 0);
    cudaStreamWaitEvent(s_side, ev_fork, 0);

    zero_kernel<<<256, 256, 0, s_side>>>();
    deg_kernel<<<(N_EDGES + 255) / 256, 256, 0, s_side>>>(src, dst);
    norm_kernel<<<(N_NODES + 255) / 256, 256, 0, s_side>>>();
    scan1_kernel<<<SCAN_B, 256, 0, s_side>>>();
    scan2_kernel<<<1, 256, 0, s_side>>>();
    scan3_kernel<<<SCAN_B, 256, 0, s_side>>>();
    fill_kernel<<<(N_EDGES + 255) / 256, 256, 0, s_side>>>(src, dst);

    // main stream: W1 fp16 convert + tensor-core GEMM1
    w1split_kernel<<<(IN_F * NH + 255) / 256, 256>>>(W1);
    gemm1_mma_kernel<<<(N_NODES + 127) / 128, 256, G1M_SMEM>>>(X);

    // join
    cudaEventRecord(ev_join, s_side);
    cudaStreamWaitEvent(0, ev_join, 0);

    // agg1 half A; gemm2(A) overlaps agg1 half B
    agg1_kernel<<<(N_HALF * 32 + 255) / 256, 256>>>(b1, 0, N_HALF);
    cudaEventRecord(ev_a, 0);
    cudaStreamWaitEvent(s_side, ev_a, 0);
    gemm2_kernel<<<1024, 256, 0, s_side>>>(W2, 0, N_HALF);

    agg1_kernel<<<((N_NODES - N_HALF) * 32 + 255) / 256, 256>>>(b1, N_HALF, N_NODES - N_HALF);
    gemm2_kernel<<<1024, 256>>>(W2, N_HALF, N_NODES - N_HALF);

    cudaEventRecord(ev_g2a, s_side);
    cudaStreamWaitEvent(0, ev_g2a, 0);

    agg2_kernel<<<(N_NODES * 32 + 255) / 256, 256>>>(b2, out);
}

// round 14
// speedup vs baseline: 1.0198x; 1.0198x over previous
#include <cuda_runtime.h>
#include <cuda_fp16.h>
#include <math.h>
#include <stdint.h>

#define N_NODES 50000
#define N_EDGES 1600000
#define IN_F    512
#define NH      128
#define NC      40
#define SCAN_B  ((N_NODES + 255) / 256)   // 196 blocks

// ---------------- static scratch (no runtime allocation) ----------------
__device__ int      g_deg_out_i[N_NODES];
__device__ int      g_deg_in_i [N_NODES];
__device__ int      g_cursor   [N_NODES];
__device__ int      g_row_ptr  [N_NODES + 1];
__device__ int      g_bsum     [256];
__device__ int2     g_edge     [N_EDGES];           // (src, bits(ns[src])) grouped by dst
__device__ float    g_ns       [N_NODES];
__device__ float    g_nd       [N_NODES];
__device__ uint16_t g_w1t_hi   [NH * IN_F];         // W1^T fp16 hi, [n][k]
__device__ uint16_t g_w1t_lo   [NH * IN_F];         // W1^T fp16 lo, [n][k]
__device__ __half   g_h1       [(size_t)N_NODES * NH]; // X@W1 (unscaled, fp16)
__device__ __half   g_h2h      [(size_t)N_NODES * NC]; // x2@W2 (unscaled, fp16)

// ---------------- small helpers ----------------
__device__ __forceinline__ uint32_t smem_to_u32(const void* p) {
    uint32_t a;
    asm("{ .reg .u64 t; cvta.to.shared.u64 t, %1; cvt.u32.u64 %0, t; }" : "=r"(a) : "l"(p));
    return a;
}
__device__ __forceinline__ void ldmx4(uint32_t* r, uint32_t addr) {
    asm volatile("ldmatrix.sync.aligned.m8n8.x4.shared.b16 {%0,%1,%2,%3}, [%4];"
                 : "=r"(r[0]), "=r"(r[1]), "=r"(r[2]), "=r"(r[3]) : "r"(addr));
}
__device__ __forceinline__ void mma_f16(float* d, const uint32_t* a, const uint32_t* b) {
    asm volatile(
        "mma.sync.aligned.m16n8k16.row.col.f32.f16.f16.f32 "
        "{%0,%1,%2,%3}, {%4,%5,%6,%7}, {%8,%9}, {%0,%1,%2,%3};"
        : "+f"(d[0]), "+f"(d[1]), "+f"(d[2]), "+f"(d[3])
        : "r"(a[0]), "r"(a[1]), "r"(a[2]), "r"(a[3]), "r"(b[0]), "r"(b[1]));
}
__device__ __forceinline__ unsigned long long pack2(float x) {
    unsigned long long r;
    asm("mov.b64 %0, {%1, %1};" : "=l"(r) : "f"(x));
    return r;
}
__device__ __forceinline__ unsigned long long packf2(float lo, float hi) {
    unsigned long long r;
    asm("mov.b64 %0, {%1, %2};" : "=l"(r) : "f"(lo), "f"(hi));
    return r;
}
__device__ __forceinline__ void fma2(unsigned long long& d,
                                     unsigned long long a, unsigned long long b) {
    asm("fma.rn.f32x2 %0, %1, %2, %0;" : "+l"(d) : "l"(a), "l"(b));
}
__device__ __forceinline__ float2 unpack2(unsigned long long v) {
    float lo, hi;
    asm("mov.b64 {%0, %1}, %2;" : "=f"(lo), "=f"(hi) : "l"(v));
    return make_float2(lo, hi);
}

// ---------------- zero counters each call ----------------
__global__ void zero_kernel() {
    int i = blockIdx.x * blockDim.x + threadIdx.x;
    int stride = gridDim.x * blockDim.x;
    for (int j = i; j < N_NODES; j += stride) {
        g_deg_out_i[j] = 0;
        g_deg_in_i [j] = 0;
        g_cursor   [j] = 0;
    }
}

__global__ void deg_kernel(const int* __restrict__ src, const int* __restrict__ dst) {
    int e = blockIdx.x * blockDim.x + threadIdx.x;
    if (e < N_EDGES) {
        atomicAdd(&g_deg_out_i[src[e]], 1);
        atomicAdd(&g_deg_in_i [dst[e]], 1);
    }
}

// ---------------- scan1 + norm fused ----------------
__global__ __launch_bounds__(256) void scan1norm_kernel() {
    __shared__ int s[256];
    int i = blockIdx.x * 256 + threadIdx.x;
    int di = (i < N_NODES) ? g_deg_in_i[i] : 0;
    if (i < N_NODES) {
        g_ns[i] = rsqrtf(fmaxf((float)g_deg_out_i[i], 1.f));
        g_nd[i] = rsqrtf(fmaxf((float)di, 1.f));
    }
    s[threadIdx.x] = di;
    __syncthreads();
    for (int off = 128; off > 0; off >>= 1) {
        if (threadIdx.x < off) s[threadIdx.x] += s[threadIdx.x + off];
        __syncthreads();
    }
    if (threadIdx.x == 0) g_bsum[blockIdx.x] = s[0];
}

// ---------------- scan2 + scan3 fused: each block re-scans bsum locally ----
__global__ __launch_bounds__(256) void scan23_kernel() {
    __shared__ int s[256];
    int t = threadIdx.x;
    // scan the 196 block partials (redundant per block, trivial cost)
    int v = (t < SCAN_B) ? g_bsum[t] : 0;
    s[t] = v;
    __syncthreads();
    for (int off = 1; off < 256; off <<= 1) {
        int u = (t >= off) ? s[t - off] : 0;
        __syncthreads();
        s[t] += u;
        __syncthreads();
    }
    int myoff = (blockIdx.x > 0) ? s[blockIdx.x - 1] : 0;   // broadcast read
    __syncthreads();
    // local scan of this block's deg chunk
    int i = blockIdx.x * 256 + t;
    int d = (i < N_NODES) ? g_deg_in_i[i] : 0;
    s[t] = d;
    __syncthreads();
    for (int off = 1; off < 256; off <<= 1) {
        int u = (t >= off) ? s[t - off] : 0;
        __syncthreads();
        s[t] += u;
        __syncthreads();
    }
    if (i < N_NODES) g_row_ptr[i] = myoff + s[t] - d;
    if (blockIdx.x == 0 && t == 0) g_row_ptr[N_NODES] = N_EDGES;
}

__global__ void fill_kernel(const int* __restrict__ src, const int* __restrict__ dst) {
    int e = blockIdx.x * blockDim.x + threadIdx.x;
    if (e < N_EDGES) {
        int d = dst[e];
        int s = src[e];
        int pos = g_row_ptr[d] + atomicAdd(&g_cursor[d], 1);
        g_edge[pos] = make_int2(s, __float_as_int(g_ns[s]));
    }
}

// ---------------- W1 -> transposed fp16 hi/lo split ----------------
__global__ void w1split_kernel(const float* __restrict__ W1) {
    int i = blockIdx.x * 256 + threadIdx.x;     // over 512*128
    if (i < IN_F * NH) {
        int k = i >> 7, n = i & 127;
        float w = W1[i];
        __half hh = __float2half_rn(w);
        float hf = __half2float(hh);
        __half hl = __float2half_rn(w - hf);
        g_w1t_hi[n * IN_F + k] = __half_as_ushort(hh);
        g_w1t_lo[n * IN_F + k] = __half_as_ushort(hl);
    }
}

// ---------------- GEMM1: h1 = X @ W1 via mma.sync fp16 2-term split --------
// CTA 128x128, 8 warps (4M x 2N), warp 32x64, K-chunk 32, 2 stages.
// smem stage (24KB): Ahi[128][32]f16 @0, Alo @8192, Bhi @16384.
#define G1M_STAGE 24576
#define G1M_SMEM  (2 * G1M_STAGE)

__global__ __launch_bounds__(256) void gemm1_mma_kernel(const float* __restrict__ X) {
    extern __shared__ char smem[];
    const uint32_t sb = smem_to_u32(smem);
    const int tid  = threadIdx.x;
    const int lane = tid & 31;
    const int wid  = tid >> 5;
    const int bm   = blockIdx.x * 128;
    const int mw   = (wid & 3) * 32;     // warp M offset
    const int nw   = (wid >> 2) * 64;    // warp N offset

    float acc[2][8][4];
    #pragma unroll
    for (int i = 0; i < 2; i++)
        #pragma unroll
        for (int j = 0; j < 8; j++)
            #pragma unroll
            for (int q = 0; q < 4; q++) acc[i][j][q] = 0.f;

    const int lrow  = tid >> 1;
    const int lhalf = tid & 1;
    const int lsw   = (lrow >> 1) & 3;

    auto load_stage = [&](int st, int k0) {
        char* stg = smem + st * G1M_STAGE;
        // A: X rows -> fp16 hi/lo
        {
            const int gr = bm + lrow;
            const bool ok = gr < N_NODES;
            const float* xp = &X[(size_t)gr * IN_F + k0 + lhalf * 16];
            #pragma unroll
            for (int q = 0; q < 4; q++) {
                float4 v = ok ? *reinterpret_cast<const float4*>(xp + q * 4)
                              : make_float4(0.f, 0.f, 0.f, 0.f);
                __half2 ha = __floats2half2_rn(v.x, v.y);
                __half2 hb = __floats2half2_rn(v.z, v.w);
                float2 haf = __half22float2(ha);
                float2 hbf = __half22float2(hb);
                __half2 la = __floats2half2_rn(v.x - haf.x, v.y - haf.y);
                __half2 lb = __floats2half2_rn(v.z - hbf.x, v.w - hbf.y);
                uint32_t hau, hbu, lau, lbu;
                memcpy(&hau, &ha, 4); memcpy(&hbu, &hb, 4);
                memcpy(&lau, &la, 4); memcpy(&lbu, &lb, 4);
                int c16 = lhalf * 2 + (q >> 1);
                uint32_t off = (uint32_t)(lrow * 64 + ((c16 ^ lsw) * 16) + (q & 1) * 8);
                *reinterpret_cast<uint2*>(stg + off)        = make_uint2(hau, hbu);
                *reinterpret_cast<uint2*>(stg + 8192 + off) = make_uint2(lau, lbu);
            }
        }
        // B: pre-converted W1^T fp16 hi, copy 32-k slice
        {
            const uint16_t* bh = &g_w1t_hi[lrow * IN_F + k0 + lhalf * 16];
            #pragma unroll
            for (int q = 0; q < 2; q++) {
                uint4 hv = *reinterpret_cast<const uint4*>(bh + q * 8);
                int c16 = lhalf * 2 + q;
                uint32_t off = (uint32_t)(lrow * 64 + ((c16 ^ lsw) * 16));
                *reinterpret_cast<uint4*>(stg + 16384 + off) = hv;
            }
        }
    };

    load_stage(0, 0);
    __syncthreads();

    const int a_rlane = lane & 15;
    const int a_kg    = lane >> 4;
    const int b_grp   = lane >> 3;
    const int b_rlane = (b_grp >> 1) * 8 + (lane & 7);
    const int b_kg    = b_grp & 1;

    const int NCHUNK = IN_F / 32;           // 16
    for (int c = 0; c < NCHUNK; c++) {
        const int cur = c & 1;
        if (c + 1 < NCHUNK) load_stage(cur ^ 1, (c + 1) * 32);

        const uint32_t sbase = sb + cur * G1M_STAGE;
        #pragma unroll
        for (int ks = 0; ks < 2; ks++) {
            uint32_t Ahi[2][4], Alo[2][4];
            #pragma unroll
            for (int mt = 0; mt < 2; mt++) {
                int row = mw + mt * 16 + a_rlane;
                uint32_t byteoff = (uint32_t)(row * 64 +
                    (((ks * 2 + a_kg) ^ ((row >> 1) & 3)) * 16));
                ldmx4(Ahi[mt], sbase + byteoff);
                ldmx4(Alo[mt], sbase + 8192 + byteoff);
            }
            uint32_t Bhi[8][2];
            #pragma unroll
            for (int ntp = 0; ntp < 4; ntp++) {
                int n = nw + ntp * 16 + b_rlane;
                uint32_t byteoff = (uint32_t)(n * 64 +
                    (((ks * 2 + b_kg) ^ ((n >> 1) & 3)) * 16));
                uint32_t rh[4];
                ldmx4(rh, sbase + 16384 + byteoff);
                Bhi[ntp * 2][0] = rh[0]; Bhi[ntp * 2][1] = rh[1];
                Bhi[ntp * 2 + 1][0] = rh[2]; Bhi[ntp * 2 + 1][1] = rh[3];
            }
            #pragma unroll
            for (int mt = 0; mt < 2; mt++)
                #pragma unroll
                for (int nt = 0; nt < 8; nt++)
                    mma_f16(acc[mt][nt], Ahi[mt], Bhi[nt]);
            #pragma unroll
            for (int mt = 0; mt < 2; mt++)
                #pragma unroll
                for (int nt = 0; nt < 8; nt++)
                    mma_f16(acc[mt][nt], Alo[mt], Bhi[nt]);
        }
        __syncthreads();
    }

    // epilogue: convert to fp16 and store half2 per 2 cols
    #pragma unroll
    for (int mt = 0; mt < 2; mt++) {
        int row = bm + mw + mt * 16 + (lane >> 2);
        #pragma unroll
        for (int nt = 0; nt < 8; nt++) {
            int col = nw + nt * 8 + (lane & 3) * 2;
            __half2 p0 = __floats2half2_rn(acc[mt][nt][0], acc[mt][nt][1]);
            __half2 p1 = __floats2half2_rn(acc[mt][nt][2], acc[mt][nt][3]);
            if (row < N_NODES)
                *reinterpret_cast<__half2*>(&g_h1[(size_t)row * NH + col]) = p0;
            if (row + 8 < N_NODES)
                *reinterpret_cast<__half2*>(&g_h1[(size_t)(row + 8) * NH + col]) = p1;
        }
    }
}

// ---------------- agg1 + gemm2 fused: warp per node, grid-stride -----------
// gather x2 (paired uint4 loads), then in-warp matvec with smem W2.
#define A1G2_BLOCKS 3125

__global__ __launch_bounds__(256) void agg1g2_kernel(const float* __restrict__ b1,
                                                     const float* __restrict__ W2) {
    __shared__ float W2s[NH * NC];        // 20KB, [k][c]
    for (int i = threadIdx.x; i < NH * NC; i += 256) W2s[i] = W2[i];
    __syncthreads();

    const int lane   = threadIdx.x & 31;
    const int half   = lane >> 4;
    const int li     = lane & 15;
    const int warp_g = (blockIdx.x * 256 + threadIdx.x) >> 5;
    const int nwarps = A1G2_BLOCKS * 8;

    for (int w = warp_g; w < N_NODES; w += nwarps) {
        int beg = g_row_ptr[w], end = g_row_ptr[w + 1];

        unsigned long long a0 = 0ull, a1 = 0ull, a2 = 0ull, a3 = 0ull;
        for (int j = beg; j < end; j += 32) {
            int n = end - j; if (n > 32) n = 32;
            int2 ed = (j + lane < end) ? g_edge[j + lane] : make_int2(0, 0);
            #pragma unroll 8
            for (int i = 0; i < n; i += 2) {
                int e  = i + half;
                int   s = __shfl_sync(0xffffffffu, ed.x, e & 31);
                float f = __int_as_float(__shfl_sync(0xffffffffu, ed.y, e & 31));
                if (e >= n) { f = 0.f; s = 0; }
                uint4 v = __ldg(reinterpret_cast<const uint4*>(&g_h1[(size_t)s * NH]) + li);
                float2 f0 = __half22float2(*reinterpret_cast<__half2*>(&v.x));
                float2 f1 = __half22float2(*reinterpret_cast<__half2*>(&v.y));
                float2 f2 = __half22float2(*reinterpret_cast<__half2*>(&v.z));
                float2 f3 = __half22float2(*reinterpret_cast<__half2*>(&v.w));
                unsigned long long pf = pack2(f);
                fma2(a0, pf, packf2(f0.x, f0.y));
                fma2(a1, pf, packf2(f1.x, f1.y));
                fma2(a2, pf, packf2(f2.x, f2.y));
                fma2(a3, pf, packf2(f3.x, f3.y));
            }
        }
        // combine halves (symmetric; all lanes get full sums for feats li*8..+8)
        unsigned long long c0 = __shfl_xor_sync(0xffffffffu, a0, 16);
        unsigned long long c1 = __shfl_xor_sync(0xffffffffu, a1, 16);
        unsigned long long c2 = __shfl_xor_sync(0xffffffffu, a2, 16);
        unsigned long long c3 = __shfl_xor_sync(0xffffffffu, a3, 16);
        float2 q0 = unpack2(a0), r0 = unpack2(c0);
        float2 q1 = unpack2(a1), r1 = unpack2(c1);
        float2 q2 = unpack2(a2), r2 = unpack2(c2);
        float2 q3 = unpack2(a3), r3 = unpack2(c3);

        float nd = g_nd[w];
        int fb = li * 8;
        float4 bA = __ldg(reinterpret_cast<const float4*>(b1 + fb));
        float4 bB = __ldg(reinterpret_cast<const float4*>(b1 + fb + 4));
        float x0 = fmaxf((q0.x + r0.x) * nd + bA.x, 0.f);
        float x1 = fmaxf((q0.y + r0.y) * nd + bA.y, 0.f);
        float x2 = fmaxf((q1.x + r1.x) * nd + bA.z, 0.f);
        float x3 = fmaxf((q1.y + r1.y) * nd + bA.w, 0.f);
        float x4 = fmaxf((q2.x + r2.x) * nd + bB.x, 0.f);
        float x5 = fmaxf((q2.y + r2.y) * nd + bB.y, 0.f);
        float x6 = fmaxf((q3.x + r3.x) * nd + bB.z, 0.f);
        float x7 = fmaxf((q3.y + r3.y) * nd + bB.w, 0.f);

        // pack x2 feats for broadcast: xu[q] = feats (fb+2q, fb+2q+1) as half2
        uint32_t xu[4];
        {
            __half2 h0 = __floats2half2_rn(x0, x1);
            __half2 h1 = __floats2half2_rn(x2, x3);
            __half2 h2v = __floats2half2_rn(x4, x5);
            __half2 h3 = __floats2half2_rn(x6, x7);
            memcpy(&xu[0], &h0, 4); memcpy(&xu[1], &h1, 4);
            memcpy(&xu[2], &h2v, 4); memcpy(&xu[3], &h3, 4);
        }

        // matvec: lane c<20 accumulates h2 cols (2c, 2c+1)
        unsigned long long macc = 0ull;
        const int c = lane;
        const bool act = c < (NC / 2);
        #pragma unroll
        for (int k = 0; k < NH; k += 2) {
            int sl = k >> 3;
            int q  = (k >> 1) & 3;
            uint32_t pr = __shfl_sync(0xffffffffu, xu[q], sl);
            float2 fv = __half22float2(*reinterpret_cast<__half2*>(&pr));
            if (act) {
                const unsigned long long* wp =
                    reinterpret_cast<const unsigned long long*>(W2s + k * NC) + c;
                fma2(macc, pack2(fv.x), wp[0]);
                fma2(macc, pack2(fv.y), wp[NC / 2]);
            }
        }
        if (act) {
            float2 p = unpack2(macc);
            *reinterpret_cast<__half2*>(&g_h2h[(size_t)w * NC + c * 2]) =
                __floats2half2_rn(p.x, p.y);
        }
    }
}

// ---------------- agg2: fp16 gather; lanes 0-19 own 2 feats each -----------
__global__ void agg2_kernel(const float* __restrict__ b2, float* __restrict__ out) {
    int t = blockIdx.x * blockDim.x + threadIdx.x;
    int w = t >> 5, lane = t & 31;
    if (w >= N_NODES) return;
    int beg = g_row_ptr[w], end = g_row_ptr[w + 1];

    unsigned long long acc = 0ull;
    const bool act = lane < (NC / 2);
    for (int j = beg; j < end; j += 32) {
        int n = end - j; if (n > 32) n = 32;
        int2 ed = (j + lane < end) ? g_edge[j + lane] : make_int2(0, 0);
        #pragma unroll 8
        for (int i = 0; i < n; i++) {
            int   s = __shfl_sync(0xffffffffu, ed.x, i);
            float f = __int_as_float(__shfl_sync(0xffffffffu, ed.y, i));
            if (act) {
                uint32_t v = __ldg(reinterpret_cast<const uint32_t*>(
                    &g_h2h[(size_t)s * NC]) + lane);
                float2 fv = __half22float2(*reinterpret_cast<__half2*>(&v));
                fma2(acc, pack2(f), packf2(fv.x, fv.y));
            }
        }
    }
    if (act) {
        float nd = g_nd[w];
        float2 p = unpack2(acc);
        float2 bb = __ldg(reinterpret_cast<const float2*>(b2) + lane);
        *reinterpret_cast<float2*>(&out[(size_t)w * NC + lane * 2]) =
            make_float2(p.x * nd + bb.x, p.y * nd + bb.y);
    }
}

// ---------------- launch ----------------
extern "C" void kernel_launch(void* const* d_in, const int* in_sizes, int n_in,
                              void* d_out, int out_size) {
    const float* X   = (const float*)d_in[0];
    const float* W1  = (const float*)d_in[1];
    const float* b1  = (const float*)d_in[2];
    const float* W2  = (const float*)d_in[3];
    const float* b2  = (const float*)d_in[4];
    const int*   src = (const int*)  d_in[5];
    const int*   dst = (const int*)  d_in[6];
    float* out = (float*)d_out;

    static cudaStream_t s_side = nullptr;
    static cudaEvent_t  ev_fork = nullptr, ev_join = nullptr;
    if (s_side == nullptr) {
        cudaStreamCreateWithFlags(&s_side, cudaStreamNonBlocking);
        cudaEventCreateWithFlags(&ev_fork, cudaEventDisableTiming);
        cudaEventCreateWithFlags(&ev_join, cudaEventDisableTiming);
        cudaFuncSetAttribute(gemm1_mma_kernel,
                             cudaFuncAttributeMaxDynamicSharedMemorySize, G1M_SMEM);
    }

    // fork: side stream runs the graph-prep chain (5 kernels)
    cudaEventRecord(ev_fork, 0);
    cudaStreamWaitEvent(s_side, ev_fork, 0);

    zero_kernel<<<256, 256, 0, s_side>>>();
    deg_kernel<<<(N_EDGES + 255) / 256, 256, 0, s_side>>>(src, dst);
    scan1norm_kernel<<<SCAN_B, 256, 0, s_side>>>();
    scan23_kernel<<<SCAN_B, 256, 0, s_side>>>();
    fill_kernel<<<(N_EDGES + 255) / 256, 256, 0, s_side>>>(src, dst);

    // main stream: W1 fp16 split + tensor-core GEMM1 (2 kernels)
    w1split_kernel<<<(IN_F * NH + 255) / 256, 256>>>(W1);
    gemm1_mma_kernel<<<(N_NODES + 127) / 128, 256, G1M_SMEM>>>(X);

    // join
    cudaEventRecord(ev_join, s_side);
    cudaStreamWaitEvent(0, ev_join, 0);

    // fused agg1+gemm2, then agg2
    agg1g2_kernel<<<A1G2_BLOCKS, 256>>>(b1, W2);
    agg2_kernel<<<(N_NODES * 32 + 255) / 256, 256>>>(b2, out);
}

// round 15
// speedup vs baseline: 1.2411x; 1.2170x over previous
#include <cuda_runtime.h>
#include <cuda_fp16.h>
#include <math.h>
#include <stdint.h>

#define N_NODES 50000
#define N_EDGES 1600000
#define IN_F    512
#define NH      128
#define NC      40
#define SCAN_B  ((N_NODES + 255) / 256)   // 196 blocks

// ---------------- static scratch (no runtime allocation) ----------------
__device__ int      g_deg_out_i[N_NODES];
__device__ int      g_deg_in_i [N_NODES];
__device__ int      g_cursor   [N_NODES];
__device__ int      g_row_ptr  [N_NODES + 1];
__device__ int      g_bsum     [256];
__device__ int2     g_edge     [N_EDGES];           // (src, half2(ns,ns) bits) by dst
__device__ float    g_ns       [N_NODES];
__device__ float    g_nd       [N_NODES];
__device__ uint16_t g_w1t_hi   [NH * IN_F];         // W1^T fp16 hi, [n][k]
__device__ uint32_t g_w2h      [NH * (NC / 2)];     // W2 as half2 pairs, [k][c2]
__device__ __half   g_h1       [(size_t)N_NODES * NH]; // X@W1 (unscaled, fp16)
__device__ __half   g_h2h      [(size_t)N_NODES * NC]; // x2@W2 (unscaled, fp16)

// ---------------- small helpers ----------------
__device__ __forceinline__ uint32_t smem_to_u32(const void* p) {
    uint32_t a;
    asm("{ .reg .u64 t; cvta.to.shared.u64 t, %1; cvt.u32.u64 %0, t; }" : "=r"(a) : "l"(p));
    return a;
}
__device__ __forceinline__ void ldmx4(uint32_t* r, uint32_t addr) {
    asm volatile("ldmatrix.sync.aligned.m8n8.x4.shared.b16 {%0,%1,%2,%3}, [%4];"
                 : "=r"(r[0]), "=r"(r[1]), "=r"(r[2]), "=r"(r[3]) : "r"(addr));
}
__device__ __forceinline__ void mma_f16(float* d, const uint32_t* a, const uint32_t* b) {
    asm volatile(
        "mma.sync.aligned.m16n8k16.row.col.f32.f16.f16.f32 "
        "{%0,%1,%2,%3}, {%4,%5,%6,%7}, {%8,%9}, {%0,%1,%2,%3};"
        : "+f"(d[0]), "+f"(d[1]), "+f"(d[2]), "+f"(d[3])
        : "r"(a[0]), "r"(a[1]), "r"(a[2]), "r"(a[3]), "r"(b[0]), "r"(b[1]));
}
__device__ __forceinline__ __half2 u2h2(uint32_t u) {
    __half2 h; memcpy(&h, &u, 4); return h;
}
__device__ __forceinline__ uint32_t h22u(__half2 h) {
    uint32_t u; memcpy(&u, &h, 4); return u;
}

// ---------------- zero counters each call ----------------
__global__ void zero_kernel() {
    int i = blockIdx.x * blockDim.x + threadIdx.x;
    int stride = gridDim.x * blockDim.x;
    for (int j = i; j < N_NODES; j += stride) {
        g_deg_out_i[j] = 0;
        g_deg_in_i [j] = 0;
        g_cursor   [j] = 0;
    }
}

__global__ void deg_kernel(const int* __restrict__ src, const int* __restrict__ dst) {
    int e = blockIdx.x * blockDim.x + threadIdx.x;
    if (e < N_EDGES) {
        atomicAdd(&g_deg_out_i[src[e]], 1);
        atomicAdd(&g_deg_in_i [dst[e]], 1);
    }
}

// ---------------- scan1 + norm fused ----------------
__global__ __launch_bounds__(256) void scan1norm_kernel() {
    __shared__ int s[256];
    int i = blockIdx.x * 256 + threadIdx.x;
    int di = (i < N_NODES) ? g_deg_in_i[i] : 0;
    if (i < N_NODES) {
        g_ns[i] = rsqrtf(fmaxf((float)g_deg_out_i[i], 1.f));
        g_nd[i] = rsqrtf(fmaxf((float)di, 1.f));
    }
    s[threadIdx.x] = di;
    __syncthreads();
    for (int off = 128; off > 0; off >>= 1) {
        if (threadIdx.x < off) s[threadIdx.x] += s[threadIdx.x + off];
        __syncthreads();
    }
    if (threadIdx.x == 0) g_bsum[blockIdx.x] = s[0];
}

// ---------------- scan2 + scan3 fused ----------------
__global__ __launch_bounds__(256) void scan23_kernel() {
    __shared__ int s[256];
    int t = threadIdx.x;
    int v = (t < SCAN_B) ? g_bsum[t] : 0;
    s[t] = v;
    __syncthreads();
    for (int off = 1; off < 256; off <<= 1) {
        int u = (t >= off) ? s[t - off] : 0;
        __syncthreads();
        s[t] += u;
        __syncthreads();
    }
    int myoff = (blockIdx.x > 0) ? s[blockIdx.x - 1] : 0;
    __syncthreads();
    int i = blockIdx.x * 256 + t;
    int d = (i < N_NODES) ? g_deg_in_i[i] : 0;
    s[t] = d;
    __syncthreads();
    for (int off = 1; off < 256; off <<= 1) {
        int u = (t >= off) ? s[t - off] : 0;
        __syncthreads();
        s[t] += u;
        __syncthreads();
    }
    if (i < N_NODES) g_row_ptr[i] = myoff + s[t] - d;
    if (blockIdx.x == 0 && t == 0) g_row_ptr[N_NODES] = N_EDGES;
}

// ---------------- fill: pack ns[src] as duplicated half2 -------------------
__global__ void fill_kernel(const int* __restrict__ src, const int* __restrict__ dst) {
    int e = blockIdx.x * blockDim.x + threadIdx.x;
    if (e < N_EDGES) {
        int d = dst[e];
        int s = src[e];
        int pos = g_row_ptr[d] + atomicAdd(&g_cursor[d], 1);
        __half h = __float2half_rn(g_ns[s]);
        __half2 hh = __half2half2(h);
        g_edge[pos] = make_int2(s, (int)h22u(hh));
    }
}

// ---------------- W1 -> transposed fp16 hi/lo; W2 -> half2 pairs -----------
__global__ void w1split_kernel(const float* __restrict__ W1,
                               const float* __restrict__ W2) {
    int i = blockIdx.x * 256 + threadIdx.x;
    if (i < IN_F * NH) {
        int k = i >> 7, n = i & 127;
        float w = W1[i];
        __half hh = __float2half_rn(w);
        g_w1t_hi[n * IN_F + k] = __half_as_ushort(hh);
    }
    if (i < NH * (NC / 2)) {
        int k = i / (NC / 2), c2 = i % (NC / 2);
        __half2 p = __floats2half2_rn(W2[k * NC + c2 * 2], W2[k * NC + c2 * 2 + 1]);
        g_w2h[i] = h22u(p);
    }
}

// NOTE: W1 lo term kernel piece -- computed inline in gemm1 loader (A split only).

// ---------------- GEMM1: h1 = X @ W1 via mma.sync fp16 2-term A-split ------
#define G1M_STAGE 24576
#define G1M_SMEM  (2 * G1M_STAGE)

__global__ __launch_bounds__(256) void gemm1_mma_kernel(const float* __restrict__ X) {
    extern __shared__ char smem[];
    const uint32_t sb = smem_to_u32(smem);
    const int tid  = threadIdx.x;
    const int lane = tid & 31;
    const int wid  = tid >> 5;
    const int bm   = blockIdx.x * 128;
    const int mw   = (wid & 3) * 32;
    const int nw   = (wid >> 2) * 64;

    float acc[2][8][4];
    #pragma unroll
    for (int i = 0; i < 2; i++)
        #pragma unroll
        for (int j = 0; j < 8; j++)
            #pragma unroll
            for (int q = 0; q < 4; q++) acc[i][j][q] = 0.f;

    const int lrow  = tid >> 1;
    const int lhalf = tid & 1;
    const int lsw   = (lrow >> 1) & 3;

    auto load_stage = [&](int st, int k0) {
        char* stg = smem + st * G1M_STAGE;
        {
            const int gr = bm + lrow;
            const bool ok = gr < N_NODES;
            const float* xp = &X[(size_t)gr * IN_F + k0 + lhalf * 16];
            #pragma unroll
            for (int q = 0; q < 4; q++) {
                float4 v = ok ? *reinterpret_cast<const float4*>(xp + q * 4)
                              : make_float4(0.f, 0.f, 0.f, 0.f);
                __half2 ha = __floats2half2_rn(v.x, v.y);
                __half2 hb = __floats2half2_rn(v.z, v.w);
                float2 haf = __half22float2(ha);
                float2 hbf = __half22float2(hb);
                __half2 la = __floats2half2_rn(v.x - haf.x, v.y - haf.y);
                __half2 lb = __floats2half2_rn(v.z - hbf.x, v.w - hbf.y);
                int c16 = lhalf * 2 + (q >> 1);
                uint32_t off = (uint32_t)(lrow * 64 + ((c16 ^ lsw) * 16) + (q & 1) * 8);
                *reinterpret_cast<uint2*>(stg + off)        = make_uint2(h22u(ha), h22u(hb));
                *reinterpret_cast<uint2*>(stg + 8192 + off) = make_uint2(h22u(la), h22u(lb));
            }
        }
        {
            const uint16_t* bh = &g_w1t_hi[lrow * IN_F + k0 + lhalf * 16];
            #pragma unroll
            for (int q = 0; q < 2; q++) {
                uint4 hv = *reinterpret_cast<const uint4*>(bh + q * 8);
                int c16 = lhalf * 2 + q;
                uint32_t off = (uint32_t)(lrow * 64 + ((c16 ^ lsw) * 16));
                *reinterpret_cast<uint4*>(stg + 16384 + off) = hv;
            }
        }
    };

    load_stage(0, 0);
    __syncthreads();

    const int a_rlane = lane & 15;
    const int a_kg    = lane >> 4;
    const int b_grp   = lane >> 3;
    const int b_rlane = (b_grp >> 1) * 8 + (lane & 7);
    const int b_kg    = b_grp & 1;

    const int NCHUNK = IN_F / 32;           // 16
    for (int c = 0; c < NCHUNK; c++) {
        const int cur = c & 1;
        if (c + 1 < NCHUNK) load_stage(cur ^ 1, (c + 1) * 32);

        const uint32_t sbase = sb + cur * G1M_STAGE;
        #pragma unroll
        for (int ks = 0; ks < 2; ks++) {
            uint32_t Ahi[2][4], Alo[2][4];
            #pragma unroll
            for (int mt = 0; mt < 2; mt++) {
                int row = mw + mt * 16 + a_rlane;
                uint32_t byteoff = (uint32_t)(row * 64 +
                    (((ks * 2 + a_kg) ^ ((row >> 1) & 3)) * 16));
                ldmx4(Ahi[mt], sbase + byteoff);
                ldmx4(Alo[mt], sbase + 8192 + byteoff);
            }
            uint32_t Bhi[8][2];
            #pragma unroll
            for (int ntp = 0; ntp < 4; ntp++) {
                int n = nw + ntp * 16 + b_rlane;
                uint32_t byteoff = (uint32_t)(n * 64 +
                    (((ks * 2 + b_kg) ^ ((n >> 1) & 3)) * 16));
                uint32_t rh[4];
                ldmx4(rh, sbase + 16384 + byteoff);
                Bhi[ntp * 2][0] = rh[0]; Bhi[ntp * 2][1] = rh[1];
                Bhi[ntp * 2 + 1][0] = rh[2]; Bhi[ntp * 2 + 1][1] = rh[3];
            }
            #pragma unroll
            for (int mt = 0; mt < 2; mt++)
                #pragma unroll
                for (int nt = 0; nt < 8; nt++)
                    mma_f16(acc[mt][nt], Ahi[mt], Bhi[nt]);
            #pragma unroll
            for (int mt = 0; mt < 2; mt++)
                #pragma unroll
                for (int nt = 0; nt < 8; nt++)
                    mma_f16(acc[mt][nt], Alo[mt], Bhi[nt]);
        }
        __syncthreads();
    }

    #pragma unroll
    for (int mt = 0; mt < 2; mt++) {
        int row = bm + mw + mt * 16 + (lane >> 2);
        #pragma unroll
        for (int nt = 0; nt < 8; nt++) {
            int col = nw + nt * 8 + (lane & 3) * 2;
            __half2 p0 = __floats2half2_rn(acc[mt][nt][0], acc[mt][nt][1]);
            __half2 p1 = __floats2half2_rn(acc[mt][nt][2], acc[mt][nt][3]);
            if (row < N_NODES)
                *reinterpret_cast<__half2*>(&g_h1[(size_t)row * NH + col]) = p0;
            if (row + 8 < N_NODES)
                *reinterpret_cast<__half2*>(&g_h1[(size_t)(row + 8) * NH + col]) = p1;
        }
    }
}

// ---------------- agg1 + gemm2 fused: HFMA2 accumulation, zero inner cvts ---
#define A1G2_BLOCKS 3125

__global__ __launch_bounds__(256) void agg1g2_kernel(const float* __restrict__ b1) {
    __shared__ uint32_t W2s[NH * (NC / 2)];      // 10KB, half2 pairs [k][c2]
    for (int i = threadIdx.x; i < NH * (NC / 2); i += 256) W2s[i] = g_w2h[i];
    __syncthreads();

    const int lane   = threadIdx.x & 31;
    const int half   = lane >> 4;
    const int li     = lane & 15;
    const int warp_g = (blockIdx.x * 256 + threadIdx.x) >> 5;
    const int nwarps = A1G2_BLOCKS * 8;

    for (int w = warp_g; w < N_NODES; w += nwarps) {
        int beg = g_row_ptr[w], end = g_row_ptr[w + 1];

        __half2 a0 = u2h2(0), a1 = u2h2(0), a2 = u2h2(0), a3 = u2h2(0);
        for (int j = beg; j < end; j += 32) {
            int n = end - j; if (n > 32) n = 32;
            int2 ed = (j + lane < end) ? g_edge[j + lane] : make_int2(0, 0);
            #pragma unroll 8
            for (int i = 0; i < n; i += 2) {
                int e = i + half;
                int      s  = __shfl_sync(0xffffffffu, ed.x, e & 31);
                uint32_t pf = (uint32_t)__shfl_sync(0xffffffffu, ed.y, e & 31);
                if (e >= n) { pf = 0u; s = 0; }
                uint4 v = __ldg(reinterpret_cast<const uint4*>(&g_h1[(size_t)s * NH]) + li);
                __half2 f2 = u2h2(pf);
                a0 = __hfma2(f2, u2h2(v.x), a0);
                a1 = __hfma2(f2, u2h2(v.y), a1);
                a2 = __hfma2(f2, u2h2(v.z), a2);
                a3 = __hfma2(f2, u2h2(v.w), a3);
            }
        }
        // combine halves (all lanes end with full sums for feats li*8..+8)
        a0 = __hadd2(a0, u2h2(__shfl_xor_sync(0xffffffffu, h22u(a0), 16)));
        a1 = __hadd2(a1, u2h2(__shfl_xor_sync(0xffffffffu, h22u(a1), 16)));
        a2 = __hadd2(a2, u2h2(__shfl_xor_sync(0xffffffffu, h22u(a2), 16)));
        a3 = __hadd2(a3, u2h2(__shfl_xor_sync(0xffffffffu, h22u(a3), 16)));
        float2 q0 = __half22float2(a0);
        float2 q1 = __half22float2(a1);
        float2 q2 = __half22float2(a2);
        float2 q3 = __half22float2(a3);

        float nd = g_nd[w];
        int fb = li * 8;
        float4 bA = __ldg(reinterpret_cast<const float4*>(b1 + fb));
        float4 bB = __ldg(reinterpret_cast<const float4*>(b1 + fb + 4));
        float x0 = fmaxf(q0.x * nd + bA.x, 0.f);
        float x1 = fmaxf(q0.y * nd + bA.y, 0.f);
        float x2 = fmaxf(q1.x * nd + bA.z, 0.f);
        float x3 = fmaxf(q1.y * nd + bA.w, 0.f);
        float x4 = fmaxf(q2.x * nd + bB.x, 0.f);
        float x5 = fmaxf(q2.y * nd + bB.y, 0.f);
        float x6 = fmaxf(q3.x * nd + bB.z, 0.f);
        float x7 = fmaxf(q3.y * nd + bB.w, 0.f);

        // pack x2 feats: xu[q] = (x_{fb+2q}, x_{fb+2q+1}) as half2
        uint32_t xu[4];
        xu[0] = h22u(__floats2half2_rn(x0, x1));
        xu[1] = h22u(__floats2half2_rn(x2, x3));
        xu[2] = h22u(__floats2half2_rn(x4, x5));
        xu[3] = h22u(__floats2half2_rn(x6, x7));

        // matvec: lane c<20 computes h2 cols (2c, 2c+1) via HFMA2
        __half2 macc = u2h2(0);
        const int c = lane;
        const bool act = c < (NC / 2);
        #pragma unroll
        for (int k = 0; k < NH; k += 2) {
            int sl = k >> 3;
            int q  = (k >> 1) & 3;
            uint32_t pr = __shfl_sync(0xffffffffu, xu[q], sl);
            __half2 ph = u2h2(pr);
            if (act) {
                __half2 xk0 = __half2half2(__low2half(ph));
                __half2 xk1 = __half2half2(__high2half(ph));
                macc = __hfma2(xk0, u2h2(W2s[k * (NC / 2) + c]), macc);
                macc = __hfma2(xk1, u2h2(W2s[(k + 1) * (NC / 2) + c]), macc);
            }
        }
        if (act)
            *reinterpret_cast<__half2*>(&g_h2h[(size_t)w * NC + c * 2]) = macc;
    }
}

// ---------------- agg2: HFMA2 accumulation; lanes 0-19 own 2 feats ---------
__global__ void agg2_kernel(const float* __restrict__ b2, float* __restrict__ out) {
    int t = blockIdx.x * blockDim.x + threadIdx.x;
    int w = t >> 5, lane = t & 31;
    if (w >= N_NODES) return;
    int beg = g_row_ptr[w], end = g_row_ptr[w + 1];

    __half2 acc = u2h2(0);
    const bool act = lane < (NC / 2);
    for (int j = beg; j < end; j += 32) {
        int n = end - j; if (n > 32) n = 32;
        int2 ed = (j + lane < end) ? g_edge[j + lane] : make_int2(0, 0);
        #pragma unroll 8
        for (int i = 0; i < n; i++) {
            int      s  = __shfl_sync(0xffffffffu, ed.x, i);
            uint32_t pf = (uint32_t)__shfl_sync(0xffffffffu, ed.y, i);
            if (act) {
                uint32_t v = __ldg(reinterpret_cast<const uint32_t*>(
                    &g_h2h[(size_t)s * NC]) + lane);
                acc = __hfma2(u2h2(pf), u2h2(v), acc);
            }
        }
    }
    if (act) {
        float nd = g_nd[w];
        float2 p = __half22float2(acc);
        float2 bb = __ldg(reinterpret_cast<const float2*>(b2) + lane);
        *reinterpret_cast<float2*>(&out[(size_t)w * NC + lane * 2]) =
            make_float2(p.x * nd + bb.x, p.y * nd + bb.y);
    }
}

// ---------------- launch ----------------
extern "C" void kernel_launch(void* const* d_in, const int* in_sizes, int n_in,
                              void* d_out, int out_size) {
    const float* X   = (const float*)d_in[0];
    const float* W1  = (const float*)d_in[1];
    const float* b1  = (const float*)d_in[2];
    const float* W2  = (const float*)d_in[3];
    const float* b2  = (const float*)d_in[4];
    const int*   src = (const int*)  d_in[5];
    const int*   dst = (const int*)  d_in[6];
    float* out = (float*)d_out;

    static cudaStream_t s_side = nullptr;
    static cudaEvent_t  ev_fork = nullptr, ev_join = nullptr;
    if (s_side == nullptr) {
        cudaStreamCreateWithFlags(&s_side, cudaStreamNonBlocking);
        cudaEventCreateWithFlags(&ev_fork, cudaEventDisableTiming);
        cudaEventCreateWithFlags(&ev_join, cudaEventDisableTiming);
        cudaFuncSetAttribute(gemm1_mma_kernel,
                             cudaFuncAttributeMaxDynamicSharedMemorySize, G1M_SMEM);
    }

    // fork: side stream runs the graph-prep chain
    cudaEventRecord(ev_fork, 0);
    cudaStreamWaitEvent(s_side, ev_fork, 0);

    zero_kernel<<<256, 256, 0, s_side>>>();
    deg_kernel<<<(N_EDGES + 255) / 256, 256, 0, s_side>>>(src, dst);
    scan1norm_kernel<<<SCAN_B, 256, 0, s_side>>>();
    scan23_kernel<<<SCAN_B, 256, 0, s_side>>>();
    fill_kernel<<<(N_EDGES + 255) / 256, 256, 0, s_side>>>(src, dst);

    // main stream: weight conversions + tensor-core GEMM1
    w1split_kernel<<<(IN_F * NH + 255) / 256, 256>>>(W1, W2);
    gemm1_mma_kernel<<<(N_NODES + 127) / 128, 256, G1M_SMEM>>>(X);

    // join
    cudaEventRecord(ev_join, s_side);
    cudaStreamWaitEvent(0, ev_join, 0);

    // fused agg1+gemm2, then agg2
    agg1g2_kernel<<<A1G2_BLOCKS, 256>>>(b1);
    agg2_kernel<<<(N_NODES * 32 + 255) / 256, 256>>>(b2, out);
}